// round 4
// baseline (speedup 1.0000x reference)
#include <cuda_runtime.h>

#define N_NODES 100000
#define E_EDGES 1600000
#define IN_C    32
#define HID     32
#define OUT_C   8
#define EDGE_D  16
#define GRAPH_D 16

// ---------------- device scratch ----------------
__device__ float g_hi [N_NODES * HID];
__device__ float g_Pr [N_NODES * EDGE_D];   // + (bias + hG) folded in
__device__ float g_Pc [N_NODES * EDGE_D];
__device__ float g_mN [N_NODES * EDGE_D];
__device__ float g_rcnt[N_NODES];
__device__ float g_ccnt[N_NODES];
__device__ float g_q  [N_NODES * OUT_C];
__device__ float g_s  [N_NODES * OUT_C];
__device__ float g_aggq[N_NODES * OUT_C];
__device__ float g_hG [GRAPH_D];
__device__ float g_pool[OUT_C];

__device__ __forceinline__ void red_add_f4(float* addr, float a, float b, float c, float d) {
    asm volatile("red.global.add.v4.f32 [%0], {%1,%2,%3,%4};"
                 :: "l"(addr), "f"(a), "f"(b), "f"(c), "f"(d) : "memory");
}

// ---------------- kernel 1: graph embedding + pool zero ----------------
__global__ void k_hG(const float* __restrict__ ga, const float* __restrict__ Wg,
                     const float* __restrict__ bg) {
    int j = threadIdx.x;
    if (j < GRAPH_D) {
        float acc = bg[j];
        #pragma unroll
        for (int k = 0; k < GRAPH_D; k++) acc += ga[k] * Wg[k * GRAPH_D + j];
        g_hG[j] = acc;
    }
    if (j < OUT_C) g_pool[j] = 0.f;
}

// ---------------- kernel 2: per-node h_i, P_r, P_c — 4 threads/node ----------------
// group lane c owns h_i channels [8c,8c+8) and P channels [4c,4c+4)
__global__ void __launch_bounds__(256)
k_nodeP(const float* __restrict__ x,
        const float* __restrict__ Wn, const float* __restrict__ bn,
        const float* __restrict__ Wea, const float* __restrict__ bea) {
    __shared__ float Wns[IN_C * HID];       // 32x32
    __shared__ float Weas[64 * EDGE_D];     // rows 0..63 of W_edge_agg
    __shared__ float bns[HID];
    __shared__ float base_s[EDGE_D];        // b_edge_agg + hG @ rows 80..95
    for (int t = threadIdx.x; t < IN_C * HID; t += blockDim.x) Wns[t] = Wn[t];
    for (int t = threadIdx.x; t < 64 * EDGE_D; t += blockDim.x) Weas[t] = Wea[t];
    if (threadIdx.x < HID) bns[threadIdx.x] = bn[threadIdx.x];
    if (threadIdx.x >= 32 && threadIdx.x < 32 + EDGE_D) {
        int j = threadIdx.x - 32;
        float b = bea[j];
        #pragma unroll
        for (int k = 0; k < GRAPH_D; k++)
            b += g_hG[k] * Wea[(80 + k) * EDGE_D + j];
        base_s[j] = b;
    }
    __syncthreads();

    int t = blockIdx.x * blockDim.x + threadIdx.x;
    int n = t >> 2;
    if (n >= N_NODES) return;
    int c = threadIdx.x & 3;

    // cooperative zero of accumulators (16 + 8 floats per node over 4 lanes)
    float4 z4 = make_float4(0.f, 0.f, 0.f, 0.f);
    *reinterpret_cast<float4*>(g_mN + (size_t)n * EDGE_D + c * 4) = z4;
    *reinterpret_cast<float2*>(g_aggq + (size_t)n * OUT_C + c * 2) = make_float2(0.f, 0.f);
    if (c == 0) g_rcnt[n] = 0.f;
    if (c == 1) g_ccnt[n] = 0.f;

    // load x row cooperatively: lane c holds x[4c..4c+4) and x[16+4c..16+4c+4)
    const float* xr = x + (size_t)n * IN_C;
    float4 xa = *reinterpret_cast<const float4*>(xr + c * 4);
    float4 xb = *reinterpret_cast<const float4*>(xr + 16 + c * 4);

    // h_i outputs j in [8c, 8c+8)
    float acc[8];
    #pragma unroll
    for (int j = 0; j < 8; j++) acc[j] = bns[c * 8 + j];
    #pragma unroll
    for (int src = 0; src < 4; src++) {
        float v[8];
        v[0] = __shfl_sync(0xFFFFFFFFu, xa.x, src, 4);
        v[1] = __shfl_sync(0xFFFFFFFFu, xa.y, src, 4);
        v[2] = __shfl_sync(0xFFFFFFFFu, xa.z, src, 4);
        v[3] = __shfl_sync(0xFFFFFFFFu, xa.w, src, 4);
        v[4] = __shfl_sync(0xFFFFFFFFu, xb.x, src, 4);
        v[5] = __shfl_sync(0xFFFFFFFFu, xb.y, src, 4);
        v[6] = __shfl_sync(0xFFFFFFFFu, xb.z, src, 4);
        v[7] = __shfl_sync(0xFFFFFFFFu, xb.w, src, 4);
        #pragma unroll
        for (int kk = 0; kk < 8; kk++) {
            int k = (kk < 4) ? (src * 4 + kk) : (16 + src * 4 + kk - 4);
            #pragma unroll
            for (int j = 0; j < 8; j++)
                acc[j] += v[kk] * Wns[k * HID + c * 8 + j];
        }
    }
    // store h_i (lane c writes 32B at offset 8c)
    float4* ho = reinterpret_cast<float4*>(g_hi + (size_t)n * HID + c * 8);
    ho[0] = make_float4(acc[0], acc[1], acc[2], acc[3]);
    ho[1] = make_float4(acc[4], acc[5], acc[6], acc[7]);

    // P_r / P_c outputs j in [4c, 4c+4); need all 32 h values -> broadcast acc
    float pr[4], pc[4];
    #pragma unroll
    for (int j = 0; j < 4; j++) { pr[j] = base_s[c * 4 + j]; pc[j] = 0.f; }
    #pragma unroll
    for (int src = 0; src < 4; src++) {
        #pragma unroll
        for (int kk = 0; kk < 8; kk++) {
            float hv = __shfl_sync(0xFFFFFFFFu, acc[kk], src, 4);
            int k = src * 8 + kk;
            #pragma unroll
            for (int j = 0; j < 4; j++) {
                pr[j] += hv * Weas[k * EDGE_D + c * 4 + j];
                pc[j] += hv * Weas[(32 + k) * EDGE_D + c * 4 + j];
            }
        }
    }
    *reinterpret_cast<float4*>(g_Pr + (size_t)n * EDGE_D + c * 4)
        = make_float4(pr[0], pr[1], pr[2], pr[3]);
    *reinterpret_cast<float4*>(g_Pc + (size_t)n * EDGE_D + c * 4)
        = make_float4(pc[0], pc[1], pc[2], pc[3]);
}

// ---------------- kernel 3: edge pass 1 — 4 threads/edge ----------------
__global__ void __launch_bounds__(256)
k_edge1(const int* __restrict__ ei,
        const float* __restrict__ edge_attr,
        const float* __restrict__ Wea) {
    __shared__ float Wc[EDGE_D * EDGE_D];   // rows 64..79 (edge_attr part)
    for (int t = threadIdx.x; t < EDGE_D * EDGE_D; t += blockDim.x)
        Wc[t] = Wea[64 * EDGE_D + t];
    __syncthreads();

    int t = blockIdx.x * blockDim.x + threadIdx.x;
    int e = t >> 2;
    if (e >= E_EDGES) return;
    int c = threadIdx.x & 3;

    int row = ei[e];
    int col = ei[E_EDGES + e];

    float4 pr = *reinterpret_cast<const float4*>(g_Pr + (size_t)row * EDGE_D + c * 4);
    float4 pc = *reinterpret_cast<const float4*>(g_Pc + (size_t)col * EDGE_D + c * 4);
    float4 ea = *reinterpret_cast<const float4*>(edge_attr + (size_t)e * EDGE_D + c * 4);

    float acc[4] = {pr.x + pc.x, pr.y + pc.y, pr.z + pc.z, pr.w + pc.w};

    #pragma unroll
    for (int src = 0; src < 4; src++) {
        float ev[4];
        ev[0] = __shfl_sync(0xFFFFFFFFu, ea.x, src, 4);
        ev[1] = __shfl_sync(0xFFFFFFFFu, ea.y, src, 4);
        ev[2] = __shfl_sync(0xFFFFFFFFu, ea.z, src, 4);
        ev[3] = __shfl_sync(0xFFFFFFFFu, ea.w, src, 4);
        #pragma unroll
        for (int kk = 0; kk < 4; kk++) {
            int k = src * 4 + kk;
            #pragma unroll
            for (int j = 0; j < 4; j++)
                acc[j] += ev[kk] * Wc[k * EDGE_D + c * 4 + j];
        }
    }
    red_add_f4(g_mN + (size_t)row * EDGE_D + c * 4,
               fmaxf(acc[0], 0.f), fmaxf(acc[1], 0.f),
               fmaxf(acc[2], 0.f), fmaxf(acc[3], 0.f));
    if (c == 0) atomicAdd(&g_rcnt[row], 1.f);
    if (c == 1) atomicAdd(&g_ccnt[col], 1.f);
}

// ---------------- kernel 4: node aggregator + SAGE projections — 4 threads/node ----------------
__global__ void __launch_bounds__(256)
k_node2(const float* __restrict__ Wna, const float* __restrict__ bna,
        const float* __restrict__ Wl,  const float* __restrict__ Wr) {
    __shared__ float Wnas[48 * HID];    // rows 0..47 (h_i and m_N parts)
    __shared__ float base_s[HID];       // b + hG @ rows 48..63
    __shared__ float Wls[HID * OUT_C];
    __shared__ float Wrs[HID * OUT_C];
    for (int t = threadIdx.x; t < 48 * HID; t += blockDim.x) Wnas[t] = Wna[t];
    for (int t = threadIdx.x; t < HID * OUT_C; t += blockDim.x) {
        Wls[t] = Wl[t]; Wrs[t] = Wr[t];
    }
    if (threadIdx.x < HID) {
        float b = bna[threadIdx.x];
        #pragma unroll
        for (int k = 0; k < GRAPH_D; k++)
            b += g_hG[k] * Wna[(48 + k) * HID + threadIdx.x];
        base_s[threadIdx.x] = b;
    }
    __syncthreads();

    int t = blockIdx.x * blockDim.x + threadIdx.x;
    int n = t >> 2;
    if (n >= N_NODES) return;
    int c = threadIdx.x & 3;

    // cooperative loads: lane c holds h[4c..4c+4), h[16+4c..), mN[4c..4c+4)
    const float* hr = g_hi + (size_t)n * HID;
    float4 ha = *reinterpret_cast<const float4*>(hr + c * 4);
    float4 hb = *reinterpret_cast<const float4*>(hr + 16 + c * 4);
    float inv_c = 1.f / fmaxf(g_rcnt[n], 1.f);
    float4 mv4 = *reinterpret_cast<const float4*>(g_mN + (size_t)n * EDGE_D + c * 4);
    mv4.x *= inv_c; mv4.y *= inv_c; mv4.z *= inv_c; mv4.w *= inv_c;

    // h_i2 outputs j in [8c, 8c+8)
    float acc[8];
    #pragma unroll
    for (int j = 0; j < 8; j++) acc[j] = base_s[c * 8 + j];
    #pragma unroll
    for (int src = 0; src < 4; src++) {
        float v[12];
        v[0]  = __shfl_sync(0xFFFFFFFFu, ha.x, src, 4);
        v[1]  = __shfl_sync(0xFFFFFFFFu, ha.y, src, 4);
        v[2]  = __shfl_sync(0xFFFFFFFFu, ha.z, src, 4);
        v[3]  = __shfl_sync(0xFFFFFFFFu, ha.w, src, 4);
        v[4]  = __shfl_sync(0xFFFFFFFFu, hb.x, src, 4);
        v[5]  = __shfl_sync(0xFFFFFFFFu, hb.y, src, 4);
        v[6]  = __shfl_sync(0xFFFFFFFFu, hb.z, src, 4);
        v[7]  = __shfl_sync(0xFFFFFFFFu, hb.w, src, 4);
        v[8]  = __shfl_sync(0xFFFFFFFFu, mv4.x, src, 4);
        v[9]  = __shfl_sync(0xFFFFFFFFu, mv4.y, src, 4);
        v[10] = __shfl_sync(0xFFFFFFFFu, mv4.z, src, 4);
        v[11] = __shfl_sync(0xFFFFFFFFu, mv4.w, src, 4);
        #pragma unroll
        for (int kk = 0; kk < 12; kk++) {
            int k = (kk < 4) ? (src * 4 + kk)
                  : (kk < 8) ? (16 + src * 4 + kk - 4)
                             : (32 + src * 4 + kk - 8);
            #pragma unroll
            for (int j = 0; j < 8; j++)
                acc[j] += v[kk] * Wnas[k * HID + c * 8 + j];
        }
    }
    #pragma unroll
    for (int j = 0; j < 8; j++) acc[j] = fmaxf(acc[j], 0.f);   // h_i2 slice

    // q/s partials over this lane's 8 k's (k = 8c..8c+8)
    float q[OUT_C], s[OUT_C];
    #pragma unroll
    for (int j = 0; j < OUT_C; j++) { q[j] = 0.f; s[j] = 0.f; }
    #pragma unroll
    for (int kk = 0; kk < 8; kk++) {
        float v = acc[kk];
        int k = c * 8 + kk;
        #pragma unroll
        for (int j = 0; j < OUT_C; j++) {
            q[j] += v * Wls[k * OUT_C + j];
            s[j] += v * Wrs[k * OUT_C + j];
        }
    }
    // butterfly reduce across the 4-lane group
    #pragma unroll
    for (int off = 1; off < 4; off <<= 1) {
        #pragma unroll
        for (int j = 0; j < OUT_C; j++) {
            q[j] += __shfl_xor_sync(0xFFFFFFFFu, q[j], off, 4);
            s[j] += __shfl_xor_sync(0xFFFFFFFFu, s[j], off, 4);
        }
    }
    // lane c writes elements [2c, 2c+2)
    *reinterpret_cast<float2*>(g_q + (size_t)n * OUT_C + c * 2) = make_float2(q[c*2], q[c*2+1]);
    *reinterpret_cast<float2*>(g_s + (size_t)n * OUT_C + c * 2) = make_float2(s[c*2], s[c*2+1]);
}

// ---------------- kernel 5: edge pass 2 — 2 threads/edge, pure reds ----------------
__global__ void __launch_bounds__(256)
k_edge2(const int* __restrict__ ei) {
    int t = blockIdx.x * blockDim.x + threadIdx.x;
    int e = t >> 1;
    if (e >= E_EDGES) return;
    int c = threadIdx.x & 1;
    int row = ei[e];
    int col = ei[E_EDGES + e];
    float4 q = *reinterpret_cast<const float4*>(g_q + (size_t)row * OUT_C + c * 4);
    red_add_f4(g_aggq + (size_t)col * OUT_C + c * 4, q.x, q.y, q.z, q.w);
}

// ---------------- kernel 6: final node output + global mean pool ----------------
__global__ void __launch_bounds__(256)
k_node3(const float* __restrict__ bl) {
    __shared__ float pool_s[OUT_C];
    __shared__ float bls[OUT_C];
    if (threadIdx.x < OUT_C) { pool_s[threadIdx.x] = 0.f; bls[threadIdx.x] = bl[threadIdx.x]; }
    __syncthreads();

    int n = blockIdx.x * blockDim.x + threadIdx.x;
    float hn[OUT_C];
    #pragma unroll
    for (int j = 0; j < OUT_C; j++) hn[j] = 0.f;
    if (n < N_NODES) {
        float inv_c = 1.f / fmaxf(g_ccnt[n], 1.f);
        const float4* ap = reinterpret_cast<const float4*>(g_aggq + (size_t)n * OUT_C);
        const float4* sp = reinterpret_cast<const float4*>(g_s + (size_t)n * OUT_C);
        float4 a0 = ap[0], a1 = ap[1], s0 = sp[0], s1 = sp[1];
        hn[0] = a0.x * inv_c + bls[0] + s0.x;
        hn[1] = a0.y * inv_c + bls[1] + s0.y;
        hn[2] = a0.z * inv_c + bls[2] + s0.z;
        hn[3] = a0.w * inv_c + bls[3] + s0.w;
        hn[4] = a1.x * inv_c + bls[4] + s1.x;
        hn[5] = a1.y * inv_c + bls[5] + s1.y;
        hn[6] = a1.z * inv_c + bls[6] + s1.z;
        hn[7] = a1.w * inv_c + bls[7] + s1.w;
    }
    #pragma unroll
    for (int j = 0; j < OUT_C; j++) {
        float v = hn[j];
        #pragma unroll
        for (int off = 16; off > 0; off >>= 1)
            v += __shfl_down_sync(0xFFFFFFFFu, v, off);
        if ((threadIdx.x & 31) == 0) atomicAdd(&pool_s[j], v);
    }
    __syncthreads();
    if (threadIdx.x < OUT_C) atomicAdd(&g_pool[threadIdx.x], pool_s[threadIdx.x]);
}

// ---------------- kernel 7: pooled mean + log_softmax ----------------
__global__ void k_final(float* __restrict__ out) {
    if (threadIdx.x == 0) {
        float p[OUT_C];
        float mx = -1e30f;
        #pragma unroll
        for (int j = 0; j < OUT_C; j++) {
            p[j] = g_pool[j] / (float)N_NODES;
            mx = fmaxf(mx, p[j]);
        }
        float se = 0.f;
        #pragma unroll
        for (int j = 0; j < OUT_C; j++) se += expf(p[j] - mx);
        float lse = mx + logf(se);
        #pragma unroll
        for (int j = 0; j < OUT_C; j++) out[j] = p[j] - lse;
    }
}

// ---------------- launch ----------------
extern "C" void kernel_launch(void* const* d_in, const int* in_sizes, int n_in,
                              void* d_out, int out_size) {
    const float* x          = (const float*)d_in[0];
    const float* edge_attr  = (const float*)d_in[1];
    const float* graph_attr = (const float*)d_in[2];
    const int*   edge_index = (const int*)  d_in[3];
    // d_in[4] = batch (all zeros) — unused
    const float* W_node     = (const float*)d_in[5];
    const float* b_node     = (const float*)d_in[6];
    const float* W_graph    = (const float*)d_in[7];
    const float* b_graph    = (const float*)d_in[8];
    const float* W_edge_agg = (const float*)d_in[9];
    const float* b_edge_agg = (const float*)d_in[10];
    const float* W_node_agg = (const float*)d_in[11];
    const float* b_node_agg = (const float*)d_in[12];
    const float* W_sage_l   = (const float*)d_in[13];
    const float* b_sage_l   = (const float*)d_in[14];
    const float* W_sage_r   = (const float*)d_in[15];
    float* out = (float*)d_out;

    const int TB = 256;
    const int nodeBlocks  = (N_NODES + TB - 1) / TB;
    const int node4Blocks = (N_NODES * 4 + TB - 1) / TB;
    const int edge1Blocks = (E_EDGES * 4 + TB - 1) / TB;
    const int edge2Blocks = (E_EDGES * 2 + TB - 1) / TB;

    k_hG<<<1, 32>>>(graph_attr, W_graph, b_graph);
    k_nodeP<<<node4Blocks, TB>>>(x, W_node, b_node, W_edge_agg, b_edge_agg);
    k_edge1<<<edge1Blocks, TB>>>(edge_index, edge_attr, W_edge_agg);
    k_node2<<<node4Blocks, TB>>>(W_node_agg, b_node_agg, W_sage_l, W_sage_r);
    k_edge2<<<edge2Blocks, TB>>>(edge_index);
    k_node3<<<nodeBlocks, TB>>>(b_sage_l);
    k_final<<<1, 32>>>(out);
}

// round 5
// speedup vs baseline: 1.1621x; 1.1621x over previous
#include <cuda_runtime.h>

#define N_NODES 100000
#define E_EDGES 1600000
#define IN_C    32
#define HID     32
#define OUT_C   8
#define EDGE_D  16
#define GRAPH_D 16

// ---------------- device scratch ----------------
__device__ float g_hi [N_NODES * HID];
__device__ float g_Pr [N_NODES * EDGE_D];   // + (bias + hG) folded in
__device__ float g_Pc [N_NODES * EDGE_D];
__device__ float g_mN [N_NODES * EDGE_D];
__device__ float g_h2 [N_NODES * HID];      // h_i2
__device__ float g_t  [N_NODES];            // sum over out-edges of 1/ccnt[col]
__device__ float g_rcnt[N_NODES];
__device__ float g_ccnt[N_NODES];
__device__ float g_hG [GRAPH_D];
__device__ float g_S0 [HID];                // sum of h_i2
__device__ float g_S1 [HID];                // sum of t * h_i2

__device__ __forceinline__ void red_add_f4(float* addr, float a, float b, float c, float d) {
    asm volatile("red.global.add.v4.f32 [%0], {%1,%2,%3,%4};"
                 :: "l"(addr), "f"(a), "f"(b), "f"(c), "f"(d) : "memory");
}

// ---------------- kernel 1: graph embedding + zero S0/S1 ----------------
__global__ void k_hG(const float* __restrict__ ga, const float* __restrict__ Wg,
                     const float* __restrict__ bg) {
    int j = threadIdx.x;
    if (j < GRAPH_D) {
        float acc = bg[j];
        #pragma unroll
        for (int k = 0; k < GRAPH_D; k++) acc += ga[k] * Wg[k * GRAPH_D + j];
        g_hG[j] = acc;
    }
    if (j < HID) { g_S0[j] = 0.f; g_S1[j] = 0.f; }
}

// ---------------- kernel 2: per-node h_i, P_r, P_c + zero accumulators ----------------
__global__ void __launch_bounds__(256)
k_nodeP(const float* __restrict__ x,
        const float* __restrict__ Wn, const float* __restrict__ bn,
        const float* __restrict__ Wea, const float* __restrict__ bea) {
    __shared__ float Wns[IN_C * HID];       // 32x32
    __shared__ float Weas[64 * EDGE_D];     // rows 0..63 of W_edge_agg
    __shared__ float bns[HID];
    __shared__ float base_s[EDGE_D];        // b_edge_agg + hG @ rows 80..95
    for (int t = threadIdx.x; t < IN_C * HID; t += blockDim.x) Wns[t] = Wn[t];
    for (int t = threadIdx.x; t < 64 * EDGE_D; t += blockDim.x) Weas[t] = Wea[t];
    if (threadIdx.x < HID) bns[threadIdx.x] = bn[threadIdx.x];
    if (threadIdx.x >= 32 && threadIdx.x < 32 + EDGE_D) {
        int j = threadIdx.x - 32;
        float b = bea[j];
        #pragma unroll
        for (int k = 0; k < GRAPH_D; k++)
            b += g_hG[k] * Wea[(80 + k) * EDGE_D + j];
        base_s[j] = b;
    }
    __syncthreads();

    int n = blockIdx.x * blockDim.x + threadIdx.x;
    if (n >= N_NODES) return;

    // zero per-node accumulators
    float4 z4 = make_float4(0.f, 0.f, 0.f, 0.f);
    float4* mz = reinterpret_cast<float4*>(g_mN + (size_t)n * EDGE_D);
    mz[0] = z4; mz[1] = z4; mz[2] = z4; mz[3] = z4;
    g_rcnt[n] = 0.f;
    g_ccnt[n] = 0.f;
    g_t[n]    = 0.f;

    float acc[HID];
    #pragma unroll
    for (int j = 0; j < HID; j++) acc[j] = bns[j];
    const float4* xr = reinterpret_cast<const float4*>(x + (size_t)n * IN_C);
    #pragma unroll
    for (int k4 = 0; k4 < IN_C / 4; k4++) {
        float4 v = xr[k4];
        float vv[4] = {v.x, v.y, v.z, v.w};
        #pragma unroll
        for (int t = 0; t < 4; t++) {
            float xv = vv[t];
            int k = k4 * 4 + t;
            #pragma unroll
            for (int j = 0; j < HID; j++) acc[j] += xv * Wns[k * HID + j];
        }
    }
    float4* ho = reinterpret_cast<float4*>(g_hi + (size_t)n * HID);
    #pragma unroll
    for (int j4 = 0; j4 < HID / 4; j4++)
        ho[j4] = make_float4(acc[j4*4], acc[j4*4+1], acc[j4*4+2], acc[j4*4+3]);

    float pr[EDGE_D], pc[EDGE_D];
    #pragma unroll
    for (int j = 0; j < EDGE_D; j++) { pr[j] = base_s[j]; pc[j] = 0.f; }
    #pragma unroll
    for (int k = 0; k < HID; k++) {
        float v = acc[k];
        #pragma unroll
        for (int j = 0; j < EDGE_D; j++) {
            pr[j] += v * Weas[k * EDGE_D + j];
            pc[j] += v * Weas[(32 + k) * EDGE_D + j];
        }
    }
    float4* po = reinterpret_cast<float4*>(g_Pr + (size_t)n * EDGE_D);
    float4* qo = reinterpret_cast<float4*>(g_Pc + (size_t)n * EDGE_D);
    #pragma unroll
    for (int j4 = 0; j4 < EDGE_D / 4; j4++) {
        po[j4] = make_float4(pr[j4*4], pr[j4*4+1], pr[j4*4+2], pr[j4*4+3]);
        qo[j4] = make_float4(pc[j4*4], pc[j4*4+1], pc[j4*4+2], pc[j4*4+3]);
    }
}

// ---------------- kernel 3: edge pass 1 — 4 threads/edge ----------------
__global__ void __launch_bounds__(256)
k_edge1(const int* __restrict__ ei,
        const float* __restrict__ edge_attr,
        const float* __restrict__ Wea) {
    __shared__ float Wc[EDGE_D * EDGE_D];   // rows 64..79 (edge_attr part)
    for (int t = threadIdx.x; t < EDGE_D * EDGE_D; t += blockDim.x)
        Wc[t] = Wea[64 * EDGE_D + t];
    __syncthreads();

    int t = blockIdx.x * blockDim.x + threadIdx.x;
    int e = t >> 2;
    if (e >= E_EDGES) return;
    int c = threadIdx.x & 3;

    int row = ei[e];
    int col = ei[E_EDGES + e];

    float4 pr = *reinterpret_cast<const float4*>(g_Pr + (size_t)row * EDGE_D + c * 4);
    float4 pc = *reinterpret_cast<const float4*>(g_Pc + (size_t)col * EDGE_D + c * 4);
    float4 ea = *reinterpret_cast<const float4*>(edge_attr + (size_t)e * EDGE_D + c * 4);

    float acc[4] = {pr.x + pc.x, pr.y + pc.y, pr.z + pc.z, pr.w + pc.w};

    #pragma unroll
    for (int src = 0; src < 4; src++) {
        float ev[4];
        ev[0] = __shfl_sync(0xFFFFFFFFu, ea.x, src, 4);
        ev[1] = __shfl_sync(0xFFFFFFFFu, ea.y, src, 4);
        ev[2] = __shfl_sync(0xFFFFFFFFu, ea.z, src, 4);
        ev[3] = __shfl_sync(0xFFFFFFFFu, ea.w, src, 4);
        #pragma unroll
        for (int kk = 0; kk < 4; kk++) {
            int k = src * 4 + kk;
            #pragma unroll
            for (int j = 0; j < 4; j++)
                acc[j] += ev[kk] * Wc[k * EDGE_D + c * 4 + j];
        }
    }
    red_add_f4(g_mN + (size_t)row * EDGE_D + c * 4,
               fmaxf(acc[0], 0.f), fmaxf(acc[1], 0.f),
               fmaxf(acc[2], 0.f), fmaxf(acc[3], 0.f));
    if (c == 0) atomicAdd(&g_rcnt[row], 1.f);
    if (c == 1) atomicAdd(&g_ccnt[col], 1.f);
}

// ---------------- kernel 4: edge pass 2 — scalar t accumulation ----------------
__global__ void __launch_bounds__(256)
k_edge2(const int* __restrict__ ei) {
    int e = blockIdx.x * blockDim.x + threadIdx.x;
    if (e >= E_EDGES) return;
    int row = ei[e];
    int col = ei[E_EDGES + e];
    float w = 1.f / fmaxf(g_ccnt[col], 1.f);
    atomicAdd(&g_t[row], w);
}

// ---------------- kernel 5: node aggregator -> h_i2 ----------------
__global__ void __launch_bounds__(256)
k_node2(const float* __restrict__ Wna, const float* __restrict__ bna) {
    __shared__ float Wnas[48 * HID];    // rows 0..47 (h_i and m_N parts)
    __shared__ float base_s[HID];       // b + hG @ rows 48..63
    for (int t = threadIdx.x; t < 48 * HID; t += blockDim.x) Wnas[t] = Wna[t];
    if (threadIdx.x < HID) {
        float b = bna[threadIdx.x];
        #pragma unroll
        for (int k = 0; k < GRAPH_D; k++)
            b += g_hG[k] * Wna[(48 + k) * HID + threadIdx.x];
        base_s[threadIdx.x] = b;
    }
    __syncthreads();

    int n = blockIdx.x * blockDim.x + threadIdx.x;
    if (n >= N_NODES) return;

    float acc[HID];
    #pragma unroll
    for (int j = 0; j < HID; j++) acc[j] = base_s[j];

    const float4* hr = reinterpret_cast<const float4*>(g_hi + (size_t)n * HID);
    #pragma unroll
    for (int k4 = 0; k4 < HID / 4; k4++) {
        float4 v = hr[k4];
        float vv[4] = {v.x, v.y, v.z, v.w};
        #pragma unroll
        for (int t = 0; t < 4; t++) {
            float hv = vv[t];
            int k = k4 * 4 + t;
            #pragma unroll
            for (int j = 0; j < HID; j++) acc[j] += hv * Wnas[k * HID + j];
        }
    }
    float inv_c = 1.f / fmaxf(g_rcnt[n], 1.f);
    const float4* mp = reinterpret_cast<const float4*>(g_mN + (size_t)n * EDGE_D);
    #pragma unroll
    for (int k4 = 0; k4 < EDGE_D / 4; k4++) {
        float4 v = mp[k4];
        float vv[4] = {v.x, v.y, v.z, v.w};
        #pragma unroll
        for (int t = 0; t < 4; t++) {
            float mv = vv[t] * inv_c;
            int k = 32 + k4 * 4 + t;
            #pragma unroll
            for (int j = 0; j < HID; j++) acc[j] += mv * Wnas[k * HID + j];
        }
    }
    float4* h2 = reinterpret_cast<float4*>(g_h2 + (size_t)n * HID);
    #pragma unroll
    for (int j4 = 0; j4 < HID / 4; j4++)
        h2[j4] = make_float4(fmaxf(acc[j4*4], 0.f),   fmaxf(acc[j4*4+1], 0.f),
                             fmaxf(acc[j4*4+2], 0.f), fmaxf(acc[j4*4+3], 0.f));
}

// ---------------- kernel 6: reduce S0 = sum h_i2, S1 = sum t*h_i2 ----------------
// lane l owns channel l; each warp walks nodes with coalesced 128B row loads.
__global__ void __launch_bounds__(256)
k_reduce() {
    int lane = threadIdx.x & 31;
    int warp = (blockIdx.x * blockDim.x + threadIdx.x) >> 5;
    int nwarps = (gridDim.x * blockDim.x) >> 5;

    float s0 = 0.f, s1 = 0.f;
    for (int n = warp; n < N_NODES; n += nwarps) {
        float h = g_h2[(size_t)n * HID + lane];
        float tv = g_t[n];
        s0 += h;
        s1 += tv * h;
    }
    atomicAdd(&g_S0[lane], s0);
    atomicAdd(&g_S1[lane], s1);
}

// ---------------- kernel 7: pooled linear + log_softmax ----------------
__global__ void k_final(const float* __restrict__ Wl, const float* __restrict__ bl,
                        const float* __restrict__ Wr, float* __restrict__ out) {
    __shared__ float p[OUT_C];
    int j = threadIdx.x;
    if (j < OUT_C) {
        float acc = 0.f;
        #pragma unroll
        for (int k = 0; k < HID; k++)
            acc += g_S1[k] * Wl[k * OUT_C + j] + g_S0[k] * Wr[k * OUT_C + j];
        p[j] = bl[j] + acc * (1.f / (float)N_NODES);
    }
    __syncthreads();
    if (j == 0) {
        float mx = -1e30f;
        #pragma unroll
        for (int i = 0; i < OUT_C; i++) mx = fmaxf(mx, p[i]);
        float se = 0.f;
        #pragma unroll
        for (int i = 0; i < OUT_C; i++) se += expf(p[i] - mx);
        float lse = mx + logf(se);
        #pragma unroll
        for (int i = 0; i < OUT_C; i++) out[i] = p[i] - lse;
    }
}

// ---------------- launch ----------------
extern "C" void kernel_launch(void* const* d_in, const int* in_sizes, int n_in,
                              void* d_out, int out_size) {
    const float* x          = (const float*)d_in[0];
    const float* edge_attr  = (const float*)d_in[1];
    const float* graph_attr = (const float*)d_in[2];
    const int*   edge_index = (const int*)  d_in[3];
    // d_in[4] = batch (all zeros) — unused
    const float* W_node     = (const float*)d_in[5];
    const float* b_node     = (const float*)d_in[6];
    const float* W_graph    = (const float*)d_in[7];
    const float* b_graph    = (const float*)d_in[8];
    const float* W_edge_agg = (const float*)d_in[9];
    const float* b_edge_agg = (const float*)d_in[10];
    const float* W_node_agg = (const float*)d_in[11];
    const float* b_node_agg = (const float*)d_in[12];
    const float* W_sage_l   = (const float*)d_in[13];
    const float* b_sage_l   = (const float*)d_in[14];
    const float* W_sage_r   = (const float*)d_in[15];
    float* out = (float*)d_out;

    const int TB = 256;
    const int nodeBlocks  = (N_NODES + TB - 1) / TB;
    const int edge1Blocks = (E_EDGES * 4 + TB - 1) / TB;
    const int edge2Blocks = (E_EDGES + TB - 1) / TB;

    k_hG<<<1, 32>>>(graph_attr, W_graph, b_graph);
    k_nodeP<<<nodeBlocks, TB>>>(x, W_node, b_node, W_edge_agg, b_edge_agg);
    k_edge1<<<edge1Blocks, TB>>>(edge_index, edge_attr, W_edge_agg);
    k_edge2<<<edge2Blocks, TB>>>(edge_index);
    k_node2<<<nodeBlocks, TB>>>(W_node_agg, b_node_agg);
    k_reduce<<<128, TB>>>();
    k_final<<<1, 32>>>(W_sage_l, b_sage_l, W_sage_r, out);
}

// round 6
// speedup vs baseline: 1.2041x; 1.0362x over previous
#include <cuda_runtime.h>

#define N_NODES 100000
#define E_EDGES 1600000
#define IN_C    32
#define HID     32
#define OUT_C   8
#define EDGE_D  16
#define GRAPH_D 16

// ---------------- device scratch ----------------
__device__ float g_hi [N_NODES * HID];
__device__ float g_Pr [N_NODES * EDGE_D];   // + (bias + hG) folded in
__device__ float g_Pc [N_NODES * EDGE_D];
__device__ float g_mN [N_NODES * EDGE_D];
__device__ float g_h2 [N_NODES * HID];      // h_i2
__device__ float g_t  [N_NODES];            // sum over out-edges of 1/ccnt[col]
__device__ float g_rcnt[N_NODES];
__device__ float g_ccnt[N_NODES];
__device__ float g_hG [GRAPH_D];
__device__ float g_S0 [HID];                // sum of h_i2
__device__ float g_S1 [HID];                // sum of t * h_i2

__device__ __forceinline__ void red_add_f4(float* addr, float a, float b, float c, float d) {
    asm volatile("red.global.add.v4.f32 [%0], {%1,%2,%3,%4};"
                 :: "l"(addr), "f"(a), "f"(b), "f"(c), "f"(d) : "memory");
}

// ---------------- kernel 1: graph embedding + zero S0/S1 ----------------
__global__ void k_hG(const float* __restrict__ ga, const float* __restrict__ Wg,
                     const float* __restrict__ bg) {
    int j = threadIdx.x;
    if (j < GRAPH_D) {
        float acc = bg[j];
        #pragma unroll
        for (int k = 0; k < GRAPH_D; k++) acc += ga[k] * Wg[k * GRAPH_D + j];
        g_hG[j] = acc;
    }
    if (j < HID) { g_S0[j] = 0.f; g_S1[j] = 0.f; }
}

// ---------------- kernel 2: per-node h_i, P_r, P_c + zero accumulators ----------------
__global__ void __launch_bounds__(256)
k_nodeP(const float* __restrict__ x,
        const float* __restrict__ Wn, const float* __restrict__ bn,
        const float* __restrict__ Wea, const float* __restrict__ bea) {
    __shared__ float Wns[IN_C * HID];       // 32x32
    __shared__ float Weas[64 * EDGE_D];     // rows 0..63 of W_edge_agg
    __shared__ float bns[HID];
    __shared__ float base_s[EDGE_D];        // b_edge_agg + hG @ rows 80..95
    for (int t = threadIdx.x; t < IN_C * HID; t += blockDim.x) Wns[t] = Wn[t];
    for (int t = threadIdx.x; t < 64 * EDGE_D; t += blockDim.x) Weas[t] = Wea[t];
    if (threadIdx.x < HID) bns[threadIdx.x] = bn[threadIdx.x];
    if (threadIdx.x >= 32 && threadIdx.x < 32 + EDGE_D) {
        int j = threadIdx.x - 32;
        float b = bea[j];
        #pragma unroll
        for (int k = 0; k < GRAPH_D; k++)
            b += g_hG[k] * Wea[(80 + k) * EDGE_D + j];
        base_s[j] = b;
    }
    __syncthreads();

    int n = blockIdx.x * blockDim.x + threadIdx.x;
    if (n >= N_NODES) return;

    // zero per-node accumulators
    float4 z4 = make_float4(0.f, 0.f, 0.f, 0.f);
    float4* mz = reinterpret_cast<float4*>(g_mN + (size_t)n * EDGE_D);
    mz[0] = z4; mz[1] = z4; mz[2] = z4; mz[3] = z4;
    g_rcnt[n] = 0.f;
    g_ccnt[n] = 0.f;
    g_t[n]    = 0.f;

    float acc[HID];
    #pragma unroll
    for (int j = 0; j < HID; j++) acc[j] = bns[j];
    const float4* xr = reinterpret_cast<const float4*>(x + (size_t)n * IN_C);
    #pragma unroll
    for (int k4 = 0; k4 < IN_C / 4; k4++) {
        float4 v = xr[k4];
        float vv[4] = {v.x, v.y, v.z, v.w};
        #pragma unroll
        for (int t = 0; t < 4; t++) {
            float xv = vv[t];
            int k = k4 * 4 + t;
            #pragma unroll
            for (int j = 0; j < HID; j++) acc[j] += xv * Wns[k * HID + j];
        }
    }
    float4* ho = reinterpret_cast<float4*>(g_hi + (size_t)n * HID);
    #pragma unroll
    for (int j4 = 0; j4 < HID / 4; j4++)
        ho[j4] = make_float4(acc[j4*4], acc[j4*4+1], acc[j4*4+2], acc[j4*4+3]);

    float pr[EDGE_D], pc[EDGE_D];
    #pragma unroll
    for (int j = 0; j < EDGE_D; j++) { pr[j] = base_s[j]; pc[j] = 0.f; }
    #pragma unroll
    for (int k = 0; k < HID; k++) {
        float v = acc[k];
        #pragma unroll
        for (int j = 0; j < EDGE_D; j++) {
            pr[j] += v * Weas[k * EDGE_D + j];
            pc[j] += v * Weas[(32 + k) * EDGE_D + j];
        }
    }
    float4* po = reinterpret_cast<float4*>(g_Pr + (size_t)n * EDGE_D);
    float4* qo = reinterpret_cast<float4*>(g_Pc + (size_t)n * EDGE_D);
    #pragma unroll
    for (int j4 = 0; j4 < EDGE_D / 4; j4++) {
        po[j4] = make_float4(pr[j4*4], pr[j4*4+1], pr[j4*4+2], pr[j4*4+3]);
        qo[j4] = make_float4(pc[j4*4], pc[j4*4+1], pc[j4*4+2], pc[j4*4+3]);
    }
}

// ---------------- kernel 3: edge pass 1 — 4 threads/edge, smem ea broadcast ----------------
// NOTE: E_EDGES*4 is an exact multiple of 256 -> no tail, no divergence.
__global__ void __launch_bounds__(256)
k_edge1(const int* __restrict__ ei,
        const float* __restrict__ edge_attr,
        const float* __restrict__ Wea) {
    __shared__ float Wc[EDGE_D * EDGE_D];   // rows 64..79 (edge_attr part)
    __shared__ float eas[256 * 4];          // staged edge_attr, float4 per thread
    for (int t = threadIdx.x; t < EDGE_D * EDGE_D; t += blockDim.x)
        Wc[t] = Wea[64 * EDGE_D + t];
    __syncthreads();

    int t = blockIdx.x * blockDim.x + threadIdx.x;
    int e = t >> 2;
    int c = threadIdx.x & 3;

    int row = ei[e];
    int col = ei[E_EDGES + e];

    float4 pr = *reinterpret_cast<const float4*>(g_Pr + (size_t)row * EDGE_D + c * 4);
    float4 pc = *reinterpret_cast<const float4*>(g_Pc + (size_t)col * EDGE_D + c * 4);
    float4 ea = *reinterpret_cast<const float4*>(edge_attr + (size_t)e * EDGE_D + c * 4);

    // stage ea so the 4-lane group can read all 16 values via smem broadcast
    reinterpret_cast<float4*>(eas)[threadIdx.x] = ea;
    __syncwarp();
    const float4* eg = reinterpret_cast<const float4*>(eas + (threadIdx.x & ~3) * 4);

    float acc[4] = {pr.x + pc.x, pr.y + pc.y, pr.z + pc.z, pr.w + pc.w};

    #pragma unroll
    for (int k4 = 0; k4 < 4; k4++) {
        float4 evv = eg[k4];
        float ev[4] = {evv.x, evv.y, evv.z, evv.w};
        #pragma unroll
        for (int kk = 0; kk < 4; kk++) {
            int k = k4 * 4 + kk;
            #pragma unroll
            for (int j = 0; j < 4; j++)
                acc[j] += ev[kk] * Wc[k * EDGE_D + c * 4 + j];
        }
    }
    red_add_f4(g_mN + (size_t)row * EDGE_D + c * 4,
               fmaxf(acc[0], 0.f), fmaxf(acc[1], 0.f),
               fmaxf(acc[2], 0.f), fmaxf(acc[3], 0.f));
    if (c == 0) atomicAdd(&g_rcnt[row], 1.f);
    if (c == 1) atomicAdd(&g_ccnt[col], 1.f);
}

// ---------------- kernel 4: edge pass 2 — scalar t accumulation ----------------
__global__ void __launch_bounds__(256)
k_edge2(const int* __restrict__ ei) {
    int e = blockIdx.x * blockDim.x + threadIdx.x;
    if (e >= E_EDGES) return;
    int row = ei[e];
    int col = ei[E_EDGES + e];
    float w = 1.f / fmaxf(g_ccnt[col], 1.f);
    atomicAdd(&g_t[row], w);
}

// ---------------- kernel 5: node aggregator -> h_i2 ----------------
__global__ void __launch_bounds__(256)
k_node2(const float* __restrict__ Wna, const float* __restrict__ bna) {
    __shared__ float Wnas[48 * HID];    // rows 0..47 (h_i and m_N parts)
    __shared__ float base_s[HID];       // b + hG @ rows 48..63
    for (int t = threadIdx.x; t < 48 * HID; t += blockDim.x) Wnas[t] = Wna[t];
    if (threadIdx.x < HID) {
        float b = bna[threadIdx.x];
        #pragma unroll
        for (int k = 0; k < GRAPH_D; k++)
            b += g_hG[k] * Wna[(48 + k) * HID + threadIdx.x];
        base_s[threadIdx.x] = b;
    }
    __syncthreads();

    int n = blockIdx.x * blockDim.x + threadIdx.x;
    if (n >= N_NODES) return;

    float acc[HID];
    #pragma unroll
    for (int j = 0; j < HID; j++) acc[j] = base_s[j];

    const float4* hr = reinterpret_cast<const float4*>(g_hi + (size_t)n * HID);
    #pragma unroll
    for (int k4 = 0; k4 < HID / 4; k4++) {
        float4 v = hr[k4];
        float vv[4] = {v.x, v.y, v.z, v.w};
        #pragma unroll
        for (int t = 0; t < 4; t++) {
            float hv = vv[t];
            int k = k4 * 4 + t;
            #pragma unroll
            for (int j = 0; j < HID; j++) acc[j] += hv * Wnas[k * HID + j];
        }
    }
    float inv_c = 1.f / fmaxf(g_rcnt[n], 1.f);
    const float4* mp = reinterpret_cast<const float4*>(g_mN + (size_t)n * EDGE_D);
    #pragma unroll
    for (int k4 = 0; k4 < EDGE_D / 4; k4++) {
        float4 v = mp[k4];
        float vv[4] = {v.x, v.y, v.z, v.w};
        #pragma unroll
        for (int t = 0; t < 4; t++) {
            float mv = vv[t] * inv_c;
            int k = 32 + k4 * 4 + t;
            #pragma unroll
            for (int j = 0; j < HID; j++) acc[j] += mv * Wnas[k * HID + j];
        }
    }
    float4* h2 = reinterpret_cast<float4*>(g_h2 + (size_t)n * HID);
    #pragma unroll
    for (int j4 = 0; j4 < HID / 4; j4++)
        h2[j4] = make_float4(fmaxf(acc[j4*4], 0.f),   fmaxf(acc[j4*4+1], 0.f),
                             fmaxf(acc[j4*4+2], 0.f), fmaxf(acc[j4*4+3], 0.f));
}

// ---------------- kernel 6: reduce S0 = sum h_i2, S1 = sum t*h_i2 ----------------
__global__ void __launch_bounds__(256)
k_reduce() {
    int lane = threadIdx.x & 31;
    int warp = (blockIdx.x * blockDim.x + threadIdx.x) >> 5;
    int nwarps = (gridDim.x * blockDim.x) >> 5;

    float s0 = 0.f, s1 = 0.f;
    for (int n = warp; n < N_NODES; n += nwarps) {
        float h = g_h2[(size_t)n * HID + lane];
        float tv = g_t[n];
        s0 += h;
        s1 += tv * h;
    }
    atomicAdd(&g_S0[lane], s0);
    atomicAdd(&g_S1[lane], s1);
}

// ---------------- kernel 7: pooled linear + log_softmax ----------------
__global__ void k_final(const float* __restrict__ Wl, const float* __restrict__ bl,
                        const float* __restrict__ Wr, float* __restrict__ out) {
    __shared__ float p[OUT_C];
    int j = threadIdx.x;
    if (j < OUT_C) {
        float acc = 0.f;
        #pragma unroll
        for (int k = 0; k < HID; k++)
            acc += g_S1[k] * Wl[k * OUT_C + j] + g_S0[k] * Wr[k * OUT_C + j];
        p[j] = bl[j] + acc * (1.f / (float)N_NODES);
    }
    __syncthreads();
    if (j == 0) {
        float mx = -1e30f;
        #pragma unroll
        for (int i = 0; i < OUT_C; i++) mx = fmaxf(mx, p[i]);
        float se = 0.f;
        #pragma unroll
        for (int i = 0; i < OUT_C; i++) se += expf(p[i] - mx);
        float lse = mx + logf(se);
        #pragma unroll
        for (int i = 0; i < OUT_C; i++) out[i] = p[i] - lse;
    }
}

// ---------------- launch ----------------
extern "C" void kernel_launch(void* const* d_in, const int* in_sizes, int n_in,
                              void* d_out, int out_size) {
    const float* x          = (const float*)d_in[0];
    const float* edge_attr  = (const float*)d_in[1];
    const float* graph_attr = (const float*)d_in[2];
    const int*   edge_index = (const int*)  d_in[3];
    // d_in[4] = batch (all zeros) — unused
    const float* W_node     = (const float*)d_in[5];
    const float* b_node     = (const float*)d_in[6];
    const float* W_graph    = (const float*)d_in[7];
    const float* b_graph    = (const float*)d_in[8];
    const float* W_edge_agg = (const float*)d_in[9];
    const float* b_edge_agg = (const float*)d_in[10];
    const float* W_node_agg = (const float*)d_in[11];
    const float* b_node_agg = (const float*)d_in[12];
    const float* W_sage_l   = (const float*)d_in[13];
    const float* b_sage_l   = (const float*)d_in[14];
    const float* W_sage_r   = (const float*)d_in[15];
    float* out = (float*)d_out;

    // one-time resource creation (host-side only; identical captured work every call)
    static cudaStream_t s2 = nullptr;
    static cudaEvent_t evFork = nullptr, evJoin = nullptr;
    if (s2 == nullptr) {
        cudaStreamCreateWithFlags(&s2, cudaStreamNonBlocking);
        cudaEventCreateWithFlags(&evFork, cudaEventDisableTiming);
        cudaEventCreateWithFlags(&evJoin, cudaEventDisableTiming);
    }

    const int TB = 256;
    const int nodeBlocks  = (N_NODES + TB - 1) / TB;
    const int edge1Blocks = (E_EDGES * 4) / TB;        // exact
    const int edge2Blocks = (E_EDGES + TB - 1) / TB;

    k_hG<<<1, 32>>>(graph_attr, W_graph, b_graph);
    k_nodeP<<<nodeBlocks, TB>>>(x, W_node, b_node, W_edge_agg, b_edge_agg);
    k_edge1<<<edge1Blocks, TB>>>(edge_index, edge_attr, W_edge_agg);

    // fork: edge2 (needs only ccnt) runs concurrently with node2
    cudaEventRecord(evFork, 0);
    cudaStreamWaitEvent(s2, evFork, 0);
    k_edge2<<<edge2Blocks, TB, 0, s2>>>(edge_index);
    cudaEventRecord(evJoin, s2);

    k_node2<<<nodeBlocks, TB>>>(W_node_agg, b_node_agg);

    // join: reduce needs both h2 (stream 0) and t (s2)
    cudaStreamWaitEvent(0, evJoin, 0);
    k_reduce<<<128, TB>>>();
    k_final<<<1, 32>>>(W_sage_l, b_sage_l, W_sage_r, out);
}